// round 13
// baseline (speedup 1.0000x reference)
#include <cuda_runtime.h>
#include <math.h>

#define NN 48
#define NP2 2304        // 48*48
#define NP3 110592      // 48^3
#define BATCH 8
#define TT 21           // 20 gain modes + 1 loss term
#define NGRP 3          // t-groups for the z-reduce stage (3 x 7)

// ---------------- device scratch (no allocations allowed) ----------------
__device__ float2 g_F[BATCH * NP3];                 // F = FFT3(f)/N^3, true index order
__device__ float2 g_W[TT * BATCH * NP3];            // per-mode xy-FFT'd slabs (slot order)
__device__ float  g_part[NGRP * BATCH * NP3];       // per-group partial Re*Im sums (slot order)

// ---------------- compile-time twiddles: W48^k = (cos, -sin)(2*pi*k/48) ----------------
__device__ constexpr float TWR[48] = {
    1.0f,           0.99144486137f, 0.96592582629f, 0.92387953251f,
    0.86602540378f, 0.79335334029f, 0.70710678119f, 0.60876142901f,
    0.5f,           0.38268343236f, 0.25881904510f, 0.13052619222f,
    0.0f,          -0.13052619222f,-0.25881904510f,-0.38268343236f,
   -0.5f,          -0.60876142901f,-0.70710678119f,-0.79335334029f,
   -0.86602540378f,-0.92387953251f,-0.96592582629f,-0.99144486137f,
   -1.0f,          -0.99144486137f,-0.96592582629f,-0.92387953251f,
   -0.86602540378f,-0.79335334029f,-0.70710678119f,-0.60876142901f,
   -0.5f,          -0.38268343236f,-0.25881904510f,-0.13052619222f,
    0.0f,           0.13052619222f, 0.25881904510f, 0.38268343236f,
    0.5f,           0.60876142901f, 0.70710678119f, 0.79335334029f,
    0.86602540378f, 0.92387953251f, 0.96592582629f, 0.99144486137f };
__device__ constexpr float TWI[48] = {
    0.0f,          -0.13052619222f,-0.25881904510f,-0.38268343236f,
   -0.5f,          -0.60876142901f,-0.70710678119f,-0.79335334029f,
   -0.86602540378f,-0.92387953251f,-0.96592582629f,-0.99144486137f,
   -1.0f,          -0.99144486137f,-0.96592582629f,-0.92387953251f,
   -0.86602540378f,-0.79335334029f,-0.70710678119f,-0.60876142901f,
   -0.5f,          -0.38268343236f,-0.25881904510f,-0.13052619222f,
    0.0f,           0.13052619222f, 0.25881904510f, 0.38268343236f,
    0.5f,           0.60876142901f, 0.70710678119f, 0.79335334029f,
    0.86602540378f, 0.92387953251f, 0.96592582629f, 0.99144486137f,
    1.0f,           0.99144486137f, 0.96592582629f, 0.92387953251f,
    0.86602540378f, 0.79335334029f, 0.70710678119f, 0.60876142901f,
    0.5f,           0.38268343236f, 0.25881904510f, 0.13052619222f };

// ---------------- complex helpers ----------------
__device__ __forceinline__ float2 caddf(float2 a, float2 b){ return make_float2(a.x+b.x, a.y+b.y); }
__device__ __forceinline__ float2 csubf(float2 a, float2 b){ return make_float2(a.x-b.x, a.y-b.y); }
__device__ __forceinline__ float2 cmulc(float2 a, float cr, float ci){
    return make_float2(fmaf(a.x, cr, -a.y*ci), fmaf(a.x, ci, a.y*cr));
}
__device__ __forceinline__ float2 cmi(float2 a){ return make_float2(a.y, -a.x); } // a * (-i)

// slot -> true output index permutation of fft48r (3x4x4 decomposition)
__device__ __forceinline__ int fperm(int s){ return 12*(s&3) + 3*((s>>2)&3) + (s>>4); }

// 16-point FFT, in place on u[0..15], output in slot order (4*m1 + m2 holds X[m1+4*m2])
__device__ __forceinline__ void fft16(float2* u){
    #pragma unroll
    for(int n2 = 0; n2 < 4; n2++){
        float2 a = u[n2], b = u[n2+4], c = u[n2+8], d = u[n2+12];
        float2 ac = caddf(a,c), amc = csubf(a,c);
        float2 bd = caddf(b,d), bmd = csubf(b,d);
        float2 x0 = caddf(ac, bd);
        float2 x2 = csubf(ac, bd);
        float2 mi = cmi(bmd);
        float2 x1 = caddf(amc, mi);
        float2 x3 = csubf(amc, mi);
        if(n2 > 0){
            x1 = cmulc(x1, TWR[3*n2], TWI[3*n2]);
            x2 = cmulc(x2, TWR[6*n2], TWI[6*n2]);
            x3 = cmulc(x3, TWR[9*n2], TWI[9*n2]);
        }
        u[n2] = x0; u[n2+4] = x1; u[n2+8] = x2; u[n2+12] = x3;
    }
    #pragma unroll
    for(int m1 = 0; m1 < 4; m1++){
        float2 a = u[4*m1], b = u[4*m1+1], c = u[4*m1+2], d = u[4*m1+3];
        float2 ac = caddf(a,c), amc = csubf(a,c);
        float2 bd = caddf(b,d), bmd = csubf(b,d);
        float2 mi = cmi(bmd);
        u[4*m1  ] = caddf(ac, bd);
        u[4*m1+1] = caddf(amc, mi);
        u[4*m1+2] = csubf(ac, bd);
        u[4*m1+3] = csubf(amc, mi);
    }
}

// 48-point forward FFT, in place, result in slot order: v[s] = X[fperm(s)]
__device__ __forceinline__ void fft48r(float2* v){
    #pragma unroll
    for(int n2 = 0; n2 < 16; n2++){
        float2 a = v[n2], b = v[16+n2], c = v[32+n2];
        float2 s = caddf(b,c), d = csubf(b,c);
        v[n2] = caddf(a, s);
        float2 t = make_float2(fmaf(-0.5f, s.x, a.x), fmaf(-0.5f, s.y, a.y));
        float ux = 0.8660254037844386f * d.x;
        float uy = 0.8660254037844386f * d.y;
        float2 y1 = make_float2(t.x + uy, t.y - ux);
        float2 y2 = make_float2(t.x - uy, t.y + ux);
        if(n2 > 0){
            y1 = cmulc(y1, TWR[n2],   TWI[n2]);     // W48^{n2}
            y2 = cmulc(y2, TWR[2*n2], TWI[2*n2]);   // W48^{2*n2}
        }
        v[16+n2] = y1; v[32+n2] = y2;
    }
    fft16(v);
    fft16(v + 16);
    fft16(v + 32);
}

// ---------------- kernels ----------------

// xy FFT of f (real input, scaled by 1/N^3), unpermuted store into g_F. 2 slabs / 96-thread block.
__global__ __launch_bounds__(96) void k_fft_xy_f(const float* __restrict__ f){
    __shared__ float2 sh[2][NN][NN+1];
    int tid = threadIdx.x;
    int s = tid / NN, l = tid % NN;
    int slab = blockIdx.x * 2 + s;
    int b = slab / NN, z = slab % NN;
    const float inv = 1.0f / (float)NP3;
    const float* src = f + b * NP3 + z * NP2;
    int x = l;
    #pragma unroll 8
    for(int y = 0; y < NN; y++){
        sh[s][y][x] = make_float2(src[y*NN + x] * inv, 0.0f);
    }
    __syncthreads();
    float2 r[NN];
    #pragma unroll
    for(int j = 0; j < NN; j++) r[j] = sh[s][l][j];
    fft48r(r);
    #pragma unroll
    for(int j = 0; j < NN; j++) sh[s][l][j] = r[j];
    __syncthreads();
    #pragma unroll
    for(int j = 0; j < NN; j++) r[j] = sh[s][j][l];
    fft48r(r);
    float2* dst = g_F + b * NP3 + z * NP2;
    int xq = fperm(l);
    #pragma unroll
    for(int j = 0; j < NN; j++) dst[fperm(j) * NN + xq] = r[j];
}

// z FFT of g_F in place (per-thread column), unpermuted store -> g_F in true frequency order.
__global__ __launch_bounds__(64) void k_fft_z_F(){
    int idx = blockIdx.x * 64 + threadIdx.x;    // [0, BATCH*NP2)
    int b = idx / NP2, c = idx % NP2;
    float2* base = g_F + b * NP3 + c;
    float2 r[NN];
    #pragma unroll
    for(int j = 0; j < NN; j++) r[j] = base[j * NP2];
    fft48r(r);
    #pragma unroll
    for(int j = 0; j < NN; j++) base[fperm(j) * NP2] = r[j];
}

// For each (t,b,z): g = F .* (phi_s + i*psi_s)  (t==20: phipsi_s + i*1),
// then xy FFT of the slab; store slab in SLOT order into g_W (coalesced).
__global__ __launch_bounds__(96) void k_mode_xy(const float* __restrict__ phi,
                                                const float* __restrict__ psi,
                                                const float* __restrict__ phipsi){
    __shared__ float2 sh[2][NN][NN+1];
    int tid = threadIdx.x;
    int s = tid / NN, l = tid % NN;
    int slab = blockIdx.x * 2 + s;
    int t   = slab / (BATCH * NN);
    int rem = slab % (BATCH * NN);
    int b = rem / NN, z = rem % NN;
    int zs = (z < 24) ? z + 24 : z - 24;
    const float2* Fsrc = g_F + b * NP3 + z * NP2;
    int x = l;
    int xs = (x < 24) ? x + 24 : x - 24;
    if(t < 20){
        const float* php = phi + t * NP3 + zs * NP2;
        const float* psp = psi + t * NP3 + zs * NP2;
        #pragma unroll 8
        for(int y = 0; y < NN; y++){
            int ys = (y < 24) ? y + 24 : y - 24;
            int js = ys * NN + xs;
            float2 F = Fsrc[y*NN + x];
            float ph = php[js], ps = psp[js];
            sh[s][y][x] = make_float2(fmaf(F.x, ph, -F.y*ps), fmaf(F.y, ph, F.x*ps));
        }
    } else {
        const float* ppp = phipsi + zs * NP2;
        #pragma unroll 8
        for(int y = 0; y < NN; y++){
            int ys = (y < 24) ? y + 24 : y - 24;
            int js = ys * NN + xs;
            float2 F = Fsrc[y*NN + x];
            float pp = ppp[js];
            sh[s][y][x] = make_float2(fmaf(F.x, pp, -F.y), fmaf(F.y, pp, F.x));
        }
    }
    __syncthreads();
    float2 r[NN];
    #pragma unroll
    for(int j = 0; j < NN; j++) r[j] = sh[s][l][j];
    fft48r(r);
    #pragma unroll
    for(int j = 0; j < NN; j++) sh[s][l][j] = r[j];
    __syncthreads();
    #pragma unroll
    for(int j = 0; j < NN; j++) r[j] = sh[s][j][l];
    fft48r(r);
    float2* dst = g_W + ((size_t)(t * BATCH + b) * NN + z) * NP2;
    #pragma unroll
    for(int j = 0; j < NN; j++) dst[j * NN + l] = r[j];   // slot order, coalesced in l
}

// z FFT per (t,b,column) + Re*Im product, accumulated over a 7-wide t-group
// (t==20 subtracts). Partial sums stay in SLOT order, coalesced store.
__global__ __launch_bounds__(96) void k_z_part(){
    int g = blockIdx.y;                                   // 0..NGRP-1
    int idx = blockIdx.x * 96 + threadIdx.x;              // [0, BATCH*NP2)
    int b = idx / NP2, c = idx % NP2;
    float acc[NN];
    #pragma unroll
    for(int j = 0; j < NN; j++) acc[j] = 0.0f;
    int t0 = g * 7;
    #pragma unroll 1
    for(int tt = 0; tt < 7; tt++){
        int t = t0 + tt;
        const float2* src = g_W + (size_t)(t * BATCH + b) * NP3 + c;
        float2 r[NN];
        #pragma unroll
        for(int j = 0; j < NN; j++) r[j] = src[(size_t)j * NP2];
        fft48r(r);
        float sg = (t == 20) ? -1.0f : 1.0f;
        #pragma unroll
        for(int j = 0; j < NN; j++) acc[j] = fmaf(sg * r[j].x, r[j].y, acc[j]);
    }
    float* dst = g_part + ((size_t)g * BATCH + b) * NP3 + c;
    #pragma unroll
    for(int j = 0; j < NN; j++) dst[(size_t)j * NP2] = acc[j];
}

// Sum the NGRP partials, scale, and un-permute (kx,ky,kz) into the output.
__global__ __launch_bounds__(256) void k_merge(const float* __restrict__ kn,
                                               float* __restrict__ out){
    int idx = blockIdx.x * 256 + threadIdx.x;             // [0, BATCH*NP3)
    const size_t S = (size_t)BATCH * NP3;
    float v = g_part[idx] + g_part[S + idx] + g_part[2*S + idx];
    float scale = 4.0f * 9.869604401089358f / (kn[0] * 25.0f);  // 4*pi^2 / kn / M^2
    int b = idx / NP3, r = idx % NP3;
    int j = r / NP2, rem = r % NP2;
    int ysl = rem / NN, xsl = rem % NN;
    out[b * NP3 + fperm(j) * NP2 + fperm(ysl) * NN + fperm(xsl)] = scale * v;
}

// ---------------- launch ----------------
extern "C" void kernel_launch(void* const* d_in, const int* in_sizes, int n_in,
                              void* d_out, int out_size){
    (void)in_sizes; (void)n_in; (void)out_size;
    const float* f      = (const float*)d_in[0];
    const float* kn     = (const float*)d_in[1];
    const float* phi    = (const float*)d_in[2];
    const float* psi    = (const float*)d_in[3];
    const float* phipsi = (const float*)d_in[4];
    float* out = (float*)d_out;

    k_fft_xy_f<<<BATCH * NN / 2, 96>>>(f);
    k_fft_z_F<<<BATCH * NP2 / 64, 64>>>();
    k_mode_xy<<<TT * BATCH * NN / 2, 96>>>(phi, psi, phipsi);
    k_z_part<<<dim3(BATCH * NP2 / 96, NGRP), 96>>>();
    k_merge<<<BATCH * NP3 / 256, 256>>>(kn, out);
}

// round 14
// speedup vs baseline: 1.0165x; 1.0165x over previous
#include <cuda_runtime.h>
#include <math.h>

#define NN 48
#define NP2 2304        // 48*48
#define NP3 110592      // 48^3
#define BATCH 8
#define TT 21           // 20 gain modes + 1 loss term
#define NGRP 3          // t-groups for the z-reduce stage (3 x 7)

// ---------------- device scratch (no allocations allowed) ----------------
__device__ float2 g_F[BATCH * NP3];                 // F = FFT3(f)/N^3, true index order
__device__ float2 g_W[TT * BATCH * NP3];            // per-mode xy-FFT'd slabs (slot order)
__device__ float  g_part[NGRP * BATCH * NP3];       // per-group partial Re*Im sums (slot order)

// ---------------- compile-time twiddles: W48^k = (cos, -sin)(2*pi*k/48) ----------------
__device__ constexpr float TWR[48] = {
    1.0f,           0.99144486137f, 0.96592582629f, 0.92387953251f,
    0.86602540378f, 0.79335334029f, 0.70710678119f, 0.60876142901f,
    0.5f,           0.38268343236f, 0.25881904510f, 0.13052619222f,
    0.0f,          -0.13052619222f,-0.25881904510f,-0.38268343236f,
   -0.5f,          -0.60876142901f,-0.70710678119f,-0.79335334029f,
   -0.86602540378f,-0.92387953251f,-0.96592582629f,-0.99144486137f,
   -1.0f,          -0.99144486137f,-0.96592582629f,-0.92387953251f,
   -0.86602540378f,-0.79335334029f,-0.70710678119f,-0.60876142901f,
   -0.5f,          -0.38268343236f,-0.25881904510f,-0.13052619222f,
    0.0f,           0.13052619222f, 0.25881904510f, 0.38268343236f,
    0.5f,           0.60876142901f, 0.70710678119f, 0.79335334029f,
    0.86602540378f, 0.92387953251f, 0.96592582629f, 0.99144486137f };
__device__ constexpr float TWI[48] = {
    0.0f,          -0.13052619222f,-0.25881904510f,-0.38268343236f,
   -0.5f,          -0.60876142901f,-0.70710678119f,-0.79335334029f,
   -0.86602540378f,-0.92387953251f,-0.96592582629f,-0.99144486137f,
   -1.0f,          -0.99144486137f,-0.96592582629f,-0.92387953251f,
   -0.86602540378f,-0.79335334029f,-0.70710678119f,-0.60876142901f,
   -0.5f,          -0.38268343236f,-0.25881904510f,-0.13052619222f,
    0.0f,           0.13052619222f, 0.25881904510f, 0.38268343236f,
    0.5f,           0.60876142901f, 0.70710678119f, 0.79335334029f,
    0.86602540378f, 0.92387953251f, 0.96592582629f, 0.99144486137f,
    1.0f,           0.99144486137f, 0.96592582629f, 0.92387953251f,
    0.86602540378f, 0.79335334029f, 0.70710678119f, 0.60876142901f,
    0.5f,           0.38268343236f, 0.25881904510f, 0.13052619222f };

// ---------------- complex helpers ----------------
__device__ __forceinline__ float2 caddf(float2 a, float2 b){ return make_float2(a.x+b.x, a.y+b.y); }
__device__ __forceinline__ float2 csubf(float2 a, float2 b){ return make_float2(a.x-b.x, a.y-b.y); }
__device__ __forceinline__ float2 cmulc(float2 a, float cr, float ci){
    return make_float2(fmaf(a.x, cr, -a.y*ci), fmaf(a.x, ci, a.y*cr));
}
__device__ __forceinline__ float2 cmi(float2 a){ return make_float2(a.y, -a.x); } // a * (-i)

// slot -> true output index permutation of fft48r (3x4x4 decomposition)
__device__ __forceinline__ int fperm(int s){ return 12*(s&3) + 3*((s>>2)&3) + (s>>4); }

// 16-point FFT, in place on u[0..15], output in slot order (4*m1 + m2 holds X[m1+4*m2])
__device__ __forceinline__ void fft16(float2* u){
    #pragma unroll
    for(int n2 = 0; n2 < 4; n2++){
        float2 a = u[n2], b = u[n2+4], c = u[n2+8], d = u[n2+12];
        float2 ac = caddf(a,c), amc = csubf(a,c);
        float2 bd = caddf(b,d), bmd = csubf(b,d);
        float2 x0 = caddf(ac, bd);
        float2 x2 = csubf(ac, bd);
        float2 mi = cmi(bmd);
        float2 x1 = caddf(amc, mi);
        float2 x3 = csubf(amc, mi);
        if(n2 > 0){
            x1 = cmulc(x1, TWR[3*n2], TWI[3*n2]);
            x2 = cmulc(x2, TWR[6*n2], TWI[6*n2]);
            x3 = cmulc(x3, TWR[9*n2], TWI[9*n2]);
        }
        u[n2] = x0; u[n2+4] = x1; u[n2+8] = x2; u[n2+12] = x3;
    }
    #pragma unroll
    for(int m1 = 0; m1 < 4; m1++){
        float2 a = u[4*m1], b = u[4*m1+1], c = u[4*m1+2], d = u[4*m1+3];
        float2 ac = caddf(a,c), amc = csubf(a,c);
        float2 bd = caddf(b,d), bmd = csubf(b,d);
        float2 mi = cmi(bmd);
        u[4*m1  ] = caddf(ac, bd);
        u[4*m1+1] = caddf(amc, mi);
        u[4*m1+2] = csubf(ac, bd);
        u[4*m1+3] = csubf(amc, mi);
    }
}

// 48-point forward FFT, in place, result in slot order: v[s] = X[fperm(s)]
__device__ __forceinline__ void fft48r(float2* v){
    #pragma unroll
    for(int n2 = 0; n2 < 16; n2++){
        float2 a = v[n2], b = v[16+n2], c = v[32+n2];
        float2 s = caddf(b,c), d = csubf(b,c);
        v[n2] = caddf(a, s);
        float2 t = make_float2(fmaf(-0.5f, s.x, a.x), fmaf(-0.5f, s.y, a.y));
        float ux = 0.8660254037844386f * d.x;
        float uy = 0.8660254037844386f * d.y;
        float2 y1 = make_float2(t.x + uy, t.y - ux);
        float2 y2 = make_float2(t.x - uy, t.y + ux);
        if(n2 > 0){
            y1 = cmulc(y1, TWR[n2],   TWI[n2]);     // W48^{n2}
            y2 = cmulc(y2, TWR[2*n2], TWI[2*n2]);   // W48^{2*n2}
        }
        v[16+n2] = y1; v[32+n2] = y2;
    }
    fft16(v);
    fft16(v + 16);
    fft16(v + 32);
}

// ---------------- kernels ----------------

// xy FFT of f (real input, scaled by 1/N^3), unpermuted store into g_F. 2 slabs / 96-thread block.
__global__ __launch_bounds__(96) void k_fft_xy_f(const float* __restrict__ f){
    __shared__ float2 sh[2][NN][NN+1];
    int tid = threadIdx.x;
    int s = tid / NN, l = tid % NN;
    int slab = blockIdx.x * 2 + s;
    int b = slab / NN, z = slab % NN;
    const float inv = 1.0f / (float)NP3;
    const float* src = f + b * NP3 + z * NP2;
    int x = l;
    #pragma unroll 8
    for(int y = 0; y < NN; y++){
        sh[s][y][x] = make_float2(src[y*NN + x] * inv, 0.0f);
    }
    __syncthreads();
    float2 r[NN];
    #pragma unroll
    for(int j = 0; j < NN; j++) r[j] = sh[s][l][j];
    fft48r(r);
    #pragma unroll
    for(int j = 0; j < NN; j++) sh[s][l][j] = r[j];
    __syncthreads();
    #pragma unroll
    for(int j = 0; j < NN; j++) r[j] = sh[s][j][l];
    fft48r(r);
    float2* dst = g_F + b * NP3 + z * NP2;
    int xq = fperm(l);
    #pragma unroll
    for(int j = 0; j < NN; j++) dst[fperm(j) * NN + xq] = r[j];
}

// z FFT of g_F in place (per-thread column), unpermuted store -> g_F in true frequency order.
__global__ __launch_bounds__(64) void k_fft_z_F(){
    int idx = blockIdx.x * 64 + threadIdx.x;    // [0, BATCH*NP2)
    int b = idx / NP2, c = idx % NP2;
    float2* base = g_F + b * NP3 + c;
    float2 r[NN];
    #pragma unroll
    for(int j = 0; j < NN; j++) r[j] = base[j * NP2];
    fft48r(r);
    #pragma unroll
    for(int j = 0; j < NN; j++) base[fperm(j) * NP2] = r[j];
}

// For each (t,b,z): g = F .* (phi_s + i*psi_s)  (t==20: phipsi_s + i*1),
// then xy FFT of the slab; store slab in SLOT order into g_W (coalesced).
__global__ __launch_bounds__(96) void k_mode_xy(const float* __restrict__ phi,
                                                const float* __restrict__ psi,
                                                const float* __restrict__ phipsi){
    __shared__ float2 sh[2][NN][NN+1];
    int tid = threadIdx.x;
    int s = tid / NN, l = tid % NN;
    int slab = blockIdx.x * 2 + s;
    int t   = slab / (BATCH * NN);
    int rem = slab % (BATCH * NN);
    int b = rem / NN, z = rem % NN;
    int zs = (z < 24) ? z + 24 : z - 24;
    const float2* Fsrc = g_F + b * NP3 + z * NP2;
    int x = l;
    int xs = (x < 24) ? x + 24 : x - 24;
    if(t < 20){
        const float* php = phi + t * NP3 + zs * NP2;
        const float* psp = psi + t * NP3 + zs * NP2;
        #pragma unroll 8
        for(int y = 0; y < NN; y++){
            int ys = (y < 24) ? y + 24 : y - 24;
            int js = ys * NN + xs;
            float2 F = Fsrc[y*NN + x];
            float ph = php[js], ps = psp[js];
            sh[s][y][x] = make_float2(fmaf(F.x, ph, -F.y*ps), fmaf(F.y, ph, F.x*ps));
        }
    } else {
        const float* ppp = phipsi + zs * NP2;
        #pragma unroll 8
        for(int y = 0; y < NN; y++){
            int ys = (y < 24) ? y + 24 : y - 24;
            int js = ys * NN + xs;
            float2 F = Fsrc[y*NN + x];
            float pp = ppp[js];
            sh[s][y][x] = make_float2(fmaf(F.x, pp, -F.y), fmaf(F.y, pp, F.x));
        }
    }
    __syncthreads();
    float2 r[NN];
    #pragma unroll
    for(int j = 0; j < NN; j++) r[j] = sh[s][l][j];
    fft48r(r);
    #pragma unroll
    for(int j = 0; j < NN; j++) sh[s][l][j] = r[j];
    __syncthreads();
    #pragma unroll
    for(int j = 0; j < NN; j++) r[j] = sh[s][j][l];
    fft48r(r);
    float2* dst = g_W + ((size_t)(t * BATCH + b) * NN + z) * NP2;
    #pragma unroll
    for(int j = 0; j < NN; j++) dst[j * NN + l] = r[j];   // slot order, coalesced in l
}

// z FFT per (t,b,column) + Re*Im product, accumulated over a 7-wide t-group
// (t==20 subtracts). Partial sums stay in SLOT order, coalesced store.
__global__ __launch_bounds__(96) void k_z_part(){
    int g = blockIdx.y;                                   // 0..NGRP-1
    int idx = blockIdx.x * 96 + threadIdx.x;              // [0, BATCH*NP2)
    int b = idx / NP2, c = idx % NP2;
    float acc[NN];
    #pragma unroll
    for(int j = 0; j < NN; j++) acc[j] = 0.0f;
    int t0 = g * 7;
    #pragma unroll 1
    for(int tt = 0; tt < 7; tt++){
        int t = t0 + tt;
        const float2* src = g_W + (size_t)(t * BATCH + b) * NP3 + c;
        float2 r[NN];
        #pragma unroll
        for(int j = 0; j < NN; j++) r[j] = src[(size_t)j * NP2];
        fft48r(r);
        float sg = (t == 20) ? -1.0f : 1.0f;
        #pragma unroll
        for(int j = 0; j < NN; j++) acc[j] = fmaf(sg * r[j].x, r[j].y, acc[j]);
    }
    float* dst = g_part + ((size_t)g * BATCH + b) * NP3 + c;
    #pragma unroll
    for(int j = 0; j < NN; j++) dst[(size_t)j * NP2] = acc[j];
}

// Sum the NGRP partials, scale, and un-permute (kx,ky,kz) into the output.
__global__ __launch_bounds__(256) void k_merge(const float* __restrict__ kn,
                                               float* __restrict__ out){
    int idx = blockIdx.x * 256 + threadIdx.x;             // [0, BATCH*NP3)
    const size_t S = (size_t)BATCH * NP3;
    float v = g_part[idx] + g_part[S + idx] + g_part[2*S + idx];
    float scale = 4.0f * 9.869604401089358f / (kn[0] * 25.0f);  // 4*pi^2 / kn / M^2
    int b = idx / NP3, r = idx % NP3;
    int j = r / NP2, rem = r % NP2;
    int ysl = rem / NN, xsl = rem % NN;
    out[b * NP3 + fperm(j) * NP2 + fperm(ysl) * NN + fperm(xsl)] = scale * v;
}

// ---------------- launch ----------------
extern "C" void kernel_launch(void* const* d_in, const int* in_sizes, int n_in,
                              void* d_out, int out_size){
    (void)in_sizes; (void)n_in; (void)out_size;
    const float* f      = (const float*)d_in[0];
    const float* kn     = (const float*)d_in[1];
    const float* phi    = (const float*)d_in[2];
    const float* psi    = (const float*)d_in[3];
    const float* phipsi = (const float*)d_in[4];
    float* out = (float*)d_out;

    k_fft_xy_f<<<BATCH * NN / 2, 96>>>(f);
    k_fft_z_F<<<BATCH * NP2 / 64, 64>>>();
    k_mode_xy<<<TT * BATCH * NN / 2, 96>>>(phi, psi, phipsi);
    k_z_part<<<dim3(BATCH * NP2 / 96, NGRP), 96>>>();
    k_merge<<<BATCH * NP3 / 256, 256>>>(kn, out);
}